// round 10
// baseline (speedup 1.0000x reference)
#include <cuda_runtime.h>
#include <math.h>

#define Bsz 128
#define Tt  256
#define Hd  1024
#define BT  (Bsz * Tt)
#define BH  (Bsz * Hd)

// Scratch (device globals: sanctioned alloc-free workaround)
__device__ __align__(16) unsigned g_xfrag[(size_t)BT * Hd]; // x as mma-fragment tf32 per token (128 MiB)
__device__ __align__(16) float g_h0f[BH];                   // final h0 (fp32, for finalize)
__device__ __align__(16) float g_part[6][BH];               // Gh0 kh0/1, Gi1 kh0/1, Gh1 kh0/1
__device__ __align__(16) float g_ringP[2][2][BH];           // Gp partial ring [parity][kh]
__device__ __align__(16) unsigned g_h0frag[2][BH];          // h0 fragment layout, parity buffers
__device__ __align__(16) unsigned g_h1frag[2][BH];          // h1 fragment layout, parity buffers
__device__ int g_cntA[16], g_cntB[16], g_cntP[2][16];       // combine counters (monotonic)
__device__ int g_barA, g_barB;                              // group phase barriers (monotonic)

// ---------------------------------------------------------------------------
// helpers
// ---------------------------------------------------------------------------
__device__ __forceinline__ unsigned f2tf(float x) {
    unsigned u;
    asm("cvt.rna.tf32.f32 %0, %1;" : "=r"(u) : "f"(x));
    return u;
}

__device__ __forceinline__ int ld_acq(const int* a) {
    int v;
    asm volatile("ld.acquire.gpu.s32 %0, [%1];" : "=r"(v) : "l"(a) : "memory");
    return v;
}

__device__ __forceinline__ void red_release(int* a) {
    asm volatile("red.release.gpu.global.add.s32 [%0], 1;" :: "l"(a) : "memory");
}

__device__ __forceinline__ void wait_ge(const int* a, int tgt) {
    if (ld_acq(a) >= tgt) return;
    while (ld_acq(a) < tgt) __nanosleep(32);
}

__device__ __forceinline__ void prefetchL2(const void* p) {
    asm volatile("prefetch.global.L2 [%0];" :: "l"(p));
}

#define MMA_TF32(C, A, B)                                                     \
    asm volatile(                                                             \
        "mma.sync.aligned.m16n8k8.row.col.f32.tf32.tf32.f32 "                 \
        "{%0,%1,%2,%3}, {%4,%5,%6,%7}, {%8,%9}, {%0,%1,%2,%3};"               \
        : "+f"((C)[0]), "+f"((C)[1]), "+f"((C)[2]), "+f"((C)[3])              \
        : "r"((A).x), "r"((A).y), "r"((A).z), "r"((A).w),                     \
          "r"((B).x), "r"((B).y))

// Fragment index of element (row b in 0..127, col n in 0..1023), m16n8k8 A layout:
// uint index = ((k8*8 + mtile)*32 + lane)*4 + reg
__device__ __forceinline__ int frag_idx(int b, int n) {
    int kc = n & 7;
    int lane = (b & 7) * 4 + (kc & 3);
    int reg  = ((b >> 3) & 1) + ((kc >> 2) << 1);
    return ((((n >> 3) << 3) + (b >> 4)) * 32 + lane) * 4 + reg;
}

// ---------------------------------------------------------------------------
// Init: zero sync state, fill initial-state fragment buffers
// ---------------------------------------------------------------------------
__global__ void init_kernel(const float* __restrict__ h0in)
{
    int idx = blockIdx.x * blockDim.x + threadIdx.x;
    if (idx < 16) { g_cntA[idx] = 0; g_cntB[idx] = 0; g_cntP[0][idx] = 0; g_cntP[1][idx] = 0; }
    if (idx == 16) { g_barA = 0; g_barB = 0; }
    for (int e = idx; e < 2 * BH; e += gridDim.x * blockDim.x) {
        int which = e >> 17;
        int r = e & (BH - 1);
        int b = r >> 10, n = r & 1023;
        unsigned v = f2tf(h0in[which * Hd + n]);
        if (which == 0) g_h0frag[1][frag_idx(b, n)] = v;
        else            g_h1frag[1][frag_idx(b, n)] = v;
    }
}

// ---------------------------------------------------------------------------
// xprep: x [B,T,H] fp32 -> per-token fragment tf32 in g_xfrag (one-shot).
// ---------------------------------------------------------------------------
__global__ void xprep_kernel(const float* __restrict__ x)
{
    const int total = BT * Hd / 4;
    for (int e = blockIdx.x * blockDim.x + threadIdx.x; e < total;
         e += gridDim.x * blockDim.x) {
        int n  = (e & 255) * 4;
        int bt = e >> 8;
        int b  = bt >> 8;
        int t  = bt & 255;
        float4 v = *(const float4*)(x + (size_t)e * 4);
        unsigned* dst = g_xfrag + (size_t)t * BH;
        dst[frag_idx(b, n + 0)] = f2tf(v.x);
        dst[frag_idx(b, n + 1)] = f2tf(v.y);
        dst[frag_idx(b, n + 2)] = f2tf(v.z);
        dst[frag_idx(b, n + 3)] = f2tf(v.w);
    }
}

// ---------------------------------------------------------------------------
// Persistent kernel. Grid = 128 blocks x 512 threads, 1 block/SM.
//   part = bid/32: 0=Gh0 [A, critical], 1=Gi1 [B], 2=Gh1 [B], 3=Gp [ring-ahead]
//   sub = bid%32: tile = sub>>1 (N-tile of 64), kh = sub&1 (K-half of 512).
// Warp layout: wm = wid&7 (M-tile of 16), kg = wid>>3 (K-group of 256).
// Sync (monotonic counters; red.release arrivals; parallel ld.acquire polls):
//   Gh0(p): entry barA>=32p; combine cntA[t]>=2(p+1) || cntP[0][t]>=p+1
//           || cntP[1][t]>=p+1 || barB>=64(p-1) (4 threads poll in parallel);
//           epilogue (2 blocks/tile, 64 rows each) -> h0frag[p&1]; arrive barA.
//   Gp(p):  entry barA>=32(p-1) (ring WAR); partial -> ringP[p&1][kh];
//           arrive cntP[kh][tile]. Runs ~1 phase ahead of the A chain.
//   B(p):   entry barA>=32p || barB>=64(p-1); combine cntB[t]>=4p;
//           epilogue -> out, h1frag[(p-1)&1]; arrive barB.
// ---------------------------------------------------------------------------
extern __shared__ unsigned smemAll[];   // Bw: 32768 uints (128KB) + red: 32KB

__global__ __launch_bounds__(512, 1) void persistent_kernel(
    const float* __restrict__ Wi, const float* __restrict__ bi,
    const float* __restrict__ Wh, const float* __restrict__ bh,
    float* __restrict__ out)
{
    const int part = blockIdx.x >> 5;     // 0..3
    const int sub  = blockIdx.x & 31;
    const int tile = sub >> 1;
    const int kh   = sub & 1;

    const int tid  = threadIdx.x;
    const int lane = tid & 31;
    const int wid  = tid >> 5;
    const int wm   = wid & 7;             // M-tile (16 rows)
    const int kg   = wid >> 3;            // K-group (32 k8-steps of this K-half)
    const int n0   = tile * 64;
    const int kstart = kh * 512;

    unsigned* Bw = smemAll;                       // [64 k8][8 nt][32 lane][2 reg]
    float4*  red = (float4*)(smemAll + 32768);    // [8 wm][8 q][32 lane]

    const float* wbase = (part == 0) ? Wh
                       : (part == 1) ? Wi + (size_t)Hd * Hd
                       : (part == 2) ? Wh + (size_t)Hd * Hd
                                     : Wi;

    // ---- one-time weight preload into fragment-ready smem ----
#pragma unroll 4
    for (int i = 0; i < 16; i++) {
        int idx = tid + 512 * i;
        int krow = idx >> 4;
        int c4   = idx & 15;
        float4 w = *(const float4*)(wbase + (size_t)(kstart + krow) * Hd + n0 + c4 * 4);
        int k8 = krow >> 3, kk = krow & 7, ntile = c4 >> 1;
        int base = ((k8 * 8 + ntile) * 32 + (c4 & 1) * 16 + (kk & 3)) * 2 + (kk >> 2);
        Bw[base +  0] = f2tf(w.x);
        Bw[base +  8] = f2tf(w.y);
        Bw[base + 16] = f2tf(w.z);
        Bw[base + 24] = f2tf(w.w);
    }
    __syncthreads();

    const bool isB = (part == 1 || part == 2);
    const int pstart = isB ? 1 : 0;
    const int pend   = isB ? Tt : Tt - 1;

    for (int p = pstart; p <= pend; ++p) {
        // ---- entry flow wait (parallel polls) ----
        if (tid < 2) {
            if (part == 0) {
                if (tid == 0 && p > 0) wait_ge(&g_barA, 32 * p);
            } else if (part == 3) {
                if (tid == 0 && p >= 2) wait_ge(&g_barA, 32 * (p - 1));
            } else {
                if (tid == 0) wait_ge(&g_barA, 32 * p);
                if (tid == 1 && p > 1) wait_ge(&g_barB, 64 * (p - 1));
            }
        }
        __syncthreads();

        const unsigned* afrag =
            (part == 0) ? g_h0frag[(p - 1) & 1] :
            (part == 1) ? g_h0frag[(p - 1) & 1] :
            (part == 2) ? g_h1frag[p & 1]
                        : g_xfrag + (size_t)p * BH;
        // this warp's disjoint A stream: k8 range [kh*64 + kg*32, +32), m-tile wm
        const uint4* abase = ((const uint4*)afrag)
                             + ((size_t)(kh * 64 + kg * 32) * 8 + wm) * 32 + lane;

        float c[8][4];
#pragma unroll
        for (int nt = 0; nt < 8; nt++)
#pragma unroll
            for (int r = 0; r < 4; r++) c[nt][r] = 0.0f;

        uint4 pa[8];
#pragma unroll
        for (int i = 0; i < 8; i++)
            pa[i] = __ldcg(abase + i * 256);

#pragma unroll 8
        for (int k8l = 0; k8l < 32; k8l++) {
            uint4 a = pa[k8l & 7];
            if (k8l < 24)
                pa[k8l & 7] = __ldcg(abase + (k8l + 8) * 256);
            const int k8 = kg * 32 + k8l;
#pragma unroll
            for (int nt = 0; nt < 8; nt++) {
                uint2 bfr = *(const uint2*)&Bw[(((k8 << 3) + nt) * 32 + lane) * 2];
                MMA_TF32(c[nt], a, bfr);
            }
        }

        // ---- kg combine: kg1 -> smem, kg0 adds; kg0 stores partial ----
        if (kg == 1) {
#pragma unroll
            for (int q = 0; q < 8; q++)
                red[(wm * 8 + q) * 32 + lane] =
                    make_float4(c[q][0], c[q][1], c[q][2], c[q][3]);
        }
        __syncthreads();
        if (kg == 0) {
            float* mp = (part == 3) ? g_ringP[p & 1][kh] : g_part[part * 2 + kh];
#pragma unroll
            for (int q = 0; q < 8; q++) {
                float4 r = red[(wm * 8 + q) * 32 + lane];
                c[q][0] += r.x; c[q][1] += r.y; c[q][2] += r.z; c[q][3] += r.w;
            }
            const int gq = lane >> 2, tq = lane & 3;
#pragma unroll
            for (int nt = 0; nt < 8; nt++) {
                int row = wm * 16 + gq;
                int col = n0 + nt * 8 + 2 * tq;
                *(float2*)&mp[(size_t)row * Hd + col] = make_float2(c[nt][0], c[nt][1]);
                *(float2*)&mp[(size_t)(row + 8) * Hd + col] = make_float2(c[nt][2], c[nt][3]);
            }
        }

        // Gp: L2-prefetch next phase's x slice while stores drain
        if (part == 3 && p + 1 < Tt) {
            const char* nx = (const char*)(g_xfrag
                              + (size_t)(p + 1) * BH + (size_t)kh * 65536);
#pragma unroll
            for (int i = 0; i < 4; i++)
                prefetchL2(nx + ((size_t)tid + i * 512) * 128);
        }

        __syncthreads();   // partial stores complete block-wide

        if (part == 3) {   // Gp: publish ring partial, next phase
            if (tid == 0) red_release(&g_cntP[kh][tile]);
            continue;
        }

        // ---- combine wait (parallel polls) ----
        if (part == 0) {
            if (tid == 0) { red_release(&g_cntA[tile]); wait_ge(&g_cntA[tile], 2 * (p + 1)); }
            else if (tid == 1) wait_ge(&g_cntP[0][tile], p + 1);
            else if (tid == 2) wait_ge(&g_cntP[1][tile], p + 1);
            else if (tid == 3 && p >= 2) wait_ge(&g_barB, 64 * (p - 1)); // WAR h0frag[p&1]
        } else {
            if (tid == 0) { red_release(&g_cntB[tile]); wait_ge(&g_cntB[tile], 4 * p); }
        }
        __syncthreads();

        // ---- distributed epilogue ----
        if (part == 0) {
            // 2 blocks/tile: rows kh*64..+64, cols n0..+64; 2 float4 per thread
            const int row = kh * 64 + (tid >> 3);
            const int nb  = n0 + (tid & 7) * 8;
            unsigned* dstf = g_h0frag[p & 1];
            const float* rp0 = g_ringP[p & 1][0];
            const float* rp1 = g_ringP[p & 1][1];
#pragma unroll
            for (int v = 0; v < 8; v += 4) {
                const int n = nb + v;
                float4 a = __ldcg((const float4*)&g_part[0][(size_t)row * Hd + n]);
                float4 b = __ldcg((const float4*)&g_part[1][(size_t)row * Hd + n]);
                float4 q = __ldcg((const float4*)&rp0[(size_t)row * Hd + n]);
                float4 s = __ldcg((const float4*)&rp1[(size_t)row * Hd + n]);
                float4 b1 = *(const float4*)&bi[n];
                float4 b2 = *(const float4*)&bh[n];
                float r0 = tanhf(a.x + b.x + q.x + s.x + b1.x + b2.x);
                float r1 = tanhf(a.y + b.y + q.y + s.y + b1.y + b2.y);
                float r2 = tanhf(a.z + b.z + q.z + s.z + b1.z + b2.z);
                float r3 = tanhf(a.w + b.w + q.w + s.w + b1.w + b2.w);
                if (p == Tt - 1)
                    *(float4*)&g_h0f[(size_t)row * Hd + n] = make_float4(r0, r1, r2, r3);
                dstf[frag_idx(row, n + 0)] = f2tf(r0);
                dstf[frag_idx(row, n + 1)] = f2tf(r1);
                dstf[frag_idx(row, n + 2)] = f2tf(r2);
                dstf[frag_idx(row, n + 3)] = f2tf(r3);
            }
        } else {
            // 4 blocks/tile: chunk of 32 rows; 1 float4 per thread
            const int chunk = (part - 1) * 2 + kh;
            const int row = chunk * 32 + (tid >> 4);
            const int n   = n0 + (tid & 15) * 4;
            const int tt  = p - 1;
            unsigned* dstf = g_h1frag[(p - 1) & 1];
            float4 s2 = __ldcg((const float4*)&g_part[2][(size_t)row * Hd + n]);
            float4 s3 = __ldcg((const float4*)&g_part[3][(size_t)row * Hd + n]);
            float4 s4 = __ldcg((const float4*)&g_part[4][(size_t)row * Hd + n]);
            float4 s5 = __ldcg((const float4*)&g_part[5][(size_t)row * Hd + n]);
            float4 b1 = *(const float4*)&bi[Hd + n];
            float4 b2 = *(const float4*)&bh[Hd + n];
            float r0 = tanhf(s2.x + s3.x + s4.x + s5.x + b1.x + b2.x);
            float r1 = tanhf(s2.y + s3.y + s4.y + s5.y + b1.y + b2.y);
            float r2 = tanhf(s2.z + s3.z + s4.z + s5.z + b1.z + b2.z);
            float r3 = tanhf(s2.w + s3.w + s4.w + s5.w + b1.w + b2.w);
            *(float4*)&out[((size_t)row * Tt + tt) * Hd + n] =
                make_float4(r0, r1, r2, r3);
            dstf[frag_idx(row, n + 0)] = f2tf(r0);
            dstf[frag_idx(row, n + 1)] = f2tf(r1);
            dstf[frag_idx(row, n + 2)] = f2tf(r2);
            dstf[frag_idx(row, n + 3)] = f2tf(r3);
        }

        // ---- group phase arrival (release publishes this block's writes) ----
        __syncthreads();
        if (tid == 0) red_release((part == 0) ? &g_barA : &g_barB);
    }
}

// ---------------------------------------------------------------------------
// Finalize: h_n[b][0] = h0_{T-1}, h_n[b][1] = h1_{T-1} (= out[:,T-1,:])
// ---------------------------------------------------------------------------
__global__ void finalize_kernel(float* __restrict__ out)
{
    int idx = blockIdx.x * blockDim.x + threadIdx.x;
    if (idx >= BH) return;
    int b = idx / Hd, h = idx % Hd;
    float* hn = out + (size_t)BT * Hd;
    hn[((size_t)b * 2 + 0) * Hd + h] = g_h0f[(size_t)b * Hd + h];
    hn[((size_t)b * 2 + 1) * Hd + h] = out[((size_t)b * Tt + (Tt - 1)) * Hd + h];
}

// ---------------------------------------------------------------------------
extern "C" void kernel_launch(void* const* d_in, const int* in_sizes, int n_in,
                              void* d_out, int out_size)
{
    const float* x    = (const float*)d_in[0];   // [B,T,H]
    const float* h0in = (const float*)d_in[1];   // [1,L,H]
    const float* Wi   = (const float*)d_in[2];   // [L,H,H]
    const float* bi   = (const float*)d_in[3];   // [L,H]
    const float* Wh   = (const float*)d_in[4];   // [L,H,H]
    const float* bh   = (const float*)d_in[5];   // [L,H]
    float* out = (float*)d_out;                  // [B,T,H] then [B,L,H]

    init_kernel<<<256, 256>>>(h0in);
    xprep_kernel<<<8192, 256>>>(x);

    cudaFuncSetAttribute(persistent_kernel,
                         cudaFuncAttributeMaxDynamicSharedMemorySize, 163840);
    persistent_kernel<<<128, 512, 163840>>>(Wi, bi, Wh, bh, out);

    finalize_kernel<<<(BH + 255) / 256, 256>>>(out);
}